// round 15
// baseline (speedup 1.0000x reference)
#include <cuda_runtime.h>
#include <cooperative_groups.h>
#include <cfloat>
#include <cstdint>

namespace cg = cooperative_groups;

// ---------------------------------------------------------------------------
// Problem-size constants
// ---------------------------------------------------------------------------
#define N_NODE_MAX 500000
#define N_EDGE_MAX 1000000
#define NREL_MAX   512
#define BATCH_MAX  64

#define SCAN_TPB   256
#define SCAN_EPT   16
#define SCAN_CHUNK 4096
#define NB_MAX     128

// k_prep block partitions
#define PREP_SETUP_BLKS 32
#define PREP_H5_BLKS    2368
#define PREP_INIT_BLKS  1696
#define PREP_BLKS (PREP_SETUP_BLKS + PREP_H5_BLKS + PREP_INIT_BLKS)

// ---------------------------------------------------------------------------
// Device scratch
// ---------------------------------------------------------------------------
__device__ float    g_agg[(size_t)N_NODE_MAX * 64];      // segment-max result
__device__ float    g_t[(size_t)N_NODE_MAX * 64];        // sum_e w_e * agg[obj_e]
__device__ float    g_wsum[N_NODE_MAX];                  // sum_e w_e (per sub)
__device__ float    g_h5[(size_t)N_NODE_MAX * 8];        // hidden@Ws (padded)
__device__ float    g_s0[N_NODE_MAX];
__device__ float    g_s1[N_NODE_MAX];
__device__ float    g_scores[N_EDGE_MAX];
__device__ float    g_Mext[64 * 66];                     // [k][c]: c<64 M, 64 v0, 65 v1
__device__ float    g_crel[NREL_MAX * 8];
__device__ float    g_cq[BATCH_MAX * 8];
__device__ unsigned g_max_enc;
__device__ float    g_sum;

// edge staging (original order) + sorted packed records
__device__ int4     g_estage[N_EDGE_MAX];   // (r_idx, rel, sub, obj)
__device__ int4     g_epack[N_EDGE_MAX];    // (sub, rel, obj, alpha_bits), obj-sorted

// counting-sort scratch (by obj)
__device__ int      g_hist[N_NODE_MAX];
__device__ int      g_off[N_NODE_MAX + 1];
__device__ int      g_cursor[N_NODE_MAX];
__device__ int      g_bsum[NB_MAX];

// ---------------------------------------------------------------------------
// Order-preserving float <-> uint encoding
// ---------------------------------------------------------------------------
__device__ __forceinline__ unsigned encf(float x) {
    unsigned u = __float_as_uint(x);
    return (u & 0x80000000u) ? ~u : (u | 0x80000000u);
}
__device__ __forceinline__ float decf(unsigned u) {
    return (u & 0x80000000u) ? __uint_as_float(u & 0x7FFFFFFFu)
                             : __uint_as_float(~u);
}

// ---------------------------------------------------------------------------
// Packed f32x2 helpers
// ---------------------------------------------------------------------------
__device__ __forceinline__ unsigned long long pack2(float a) {
    unsigned long long r;
    asm("mov.b64 %0, {%1, %1};" : "=l"(r) : "r"(__float_as_uint(a)));
    return r;
}
__device__ __forceinline__ void ffma2(unsigned long long& d,
                                      unsigned long long a,
                                      unsigned long long b) {
    asm("fma.rn.f32x2 %0, %1, %2, %0;" : "+l"(d) : "l"(a), "l"(b));
}
__device__ __forceinline__ float2 unpack2(unsigned long long v) {
    unsigned lo, hi;
    asm("mov.b64 {%0, %1}, %2;" : "=r"(lo), "=r"(hi) : "l"(v));
    return make_float2(__uint_as_float(lo), __uint_as_float(hi));
}

// ---------------------------------------------------------------------------
// K_PREP: fused setup + h5 + init (independent work, blockIdx-partitioned)
// ---------------------------------------------------------------------------
__global__ void __launch_bounds__(256)
k_prep(const float* __restrict__ Wh,
       const float* __restrict__ Wnode,
       const float* __restrict__ attn_w,
       const float* __restrict__ rela,
       const float* __restrict__ Wr,
       const float* __restrict__ Wqr_w,
       const float* __restrict__ Wqr_b,
       const int*   __restrict__ q_rel,
       const float* __restrict__ hidden,
       const float* __restrict__ Ws,
       int nrel, int batch, int n_node)
{
    const int b = blockIdx.x;

    if (b < PREP_SETUP_BLKS) {
        // --- setup tables ---
        int gtid   = b * blockDim.x + threadIdx.x;
        int stride = PREP_SETUP_BLKS * blockDim.x;

        for (int i = gtid; i < 64 * 66; i += stride) {
            int k = i / 66, c = i % 66;
            float s = 0.f;
            if (c < 64) {
                #pragma unroll 8
                for (int j = 0; j < 64; j++) s += Wh[k * 64 + j] * Wnode[j * 64 + c];
            } else {
                const float* w = attn_w + (c - 64) * 64;
                #pragma unroll 8
                for (int j = 0; j < 64; j++) s += Wh[k * 64 + j] * w[j];
            }
            g_Mext[i] = s;
        }
        for (int i = gtid; i < nrel * 5; i += stride) {
            int r = i / 5, j = i % 5;
            float s = 0.f;
            #pragma unroll 8
            for (int k = 0; k < 64; k++) s += rela[r * 64 + k] * Wr[k * 5 + j];
            g_crel[r * 8 + j] = s;
        }
        for (int i = gtid; i < batch * 5; i += stride) {
            int bb = i / 5, j = i % 5;
            int qr = q_rel[bb];
            float s = Wqr_b[j];
            #pragma unroll 8
            for (int k = 0; k < 64; k++) s += rela[qr * 64 + k] * Wqr_w[k * 5 + j];
            g_cq[bb * 8 + j] = s;
        }
        if (gtid == 0) { g_max_enc = 0u; g_sum = 0.f; }
    } else if (b < PREP_SETUP_BLKS + PREP_H5_BLKS) {
        // --- H5 = hidden @ Ws (warp per node) ---
        const int lane = threadIdx.x & 31;
        float wsa[5], wsb[5];
        #pragma unroll
        for (int j = 0; j < 5; j++) {
            wsa[j] = __ldg(Ws + (2 * lane) * 5 + j);
            wsb[j] = __ldg(Ws + (2 * lane + 1) * 5 + j);
        }
        const int warps_total = PREP_H5_BLKS * (blockDim.x >> 5);
        int w = (b - PREP_SETUP_BLKS) * (blockDim.x >> 5) + (threadIdx.x >> 5);

        for (int node = w; node < n_node; node += warps_total) {
            const float2 h = *reinterpret_cast<const float2*>(
                hidden + (size_t)node * 64 + 2 * lane);
            float p0 = h.x * wsa[0] + h.y * wsb[0];
            float p1 = h.x * wsa[1] + h.y * wsb[1];
            float p2 = h.x * wsa[2] + h.y * wsb[2];
            float p3 = h.x * wsa[3] + h.y * wsb[3];
            float p4 = h.x * wsa[4] + h.y * wsb[4];
            #pragma unroll
            for (int off = 16; off > 0; off >>= 1) {
                p0 += __shfl_xor_sync(0xFFFFFFFFu, p0, off);
                p1 += __shfl_xor_sync(0xFFFFFFFFu, p1, off);
                p2 += __shfl_xor_sync(0xFFFFFFFFu, p2, off);
                p3 += __shfl_xor_sync(0xFFFFFFFFu, p3, off);
                p4 += __shfl_xor_sync(0xFFFFFFFFu, p4, off);
            }
            if (lane == 0) {
                float* dst = g_h5 + (size_t)node * 8;
                *reinterpret_cast<float4*>(dst) = make_float4(p0, p1, p2, p3);
                dst[4] = p4;
            }
        }
    } else {
        // --- init zeros: t, wsum, hist ---
        size_t gtid   = (size_t)(b - PREP_SETUP_BLKS - PREP_H5_BLKS) * blockDim.x
                        + threadIdx.x;
        size_t stride = (size_t)PREP_INIT_BLKS * blockDim.x;

        float4* tp = reinterpret_cast<float4*>(g_t);
        size_t  nt = (size_t)n_node * 16;
        float4  zv = make_float4(0.f, 0.f, 0.f, 0.f);
        for (size_t t = gtid; t < nt; t += stride) tp[t] = zv;
        for (size_t t = gtid; t < (size_t)n_node; t += stride) {
            g_hist[t] = 0;
            g_wsum[t] = 0.f;
        }
    }
}

// ---------------------------------------------------------------------------
// K2a: histogram over obj + stage compact edge tuples
// ---------------------------------------------------------------------------
__global__ void __launch_bounds__(256)
k_hist(const int* __restrict__ edges, int n_edge)
{
    int e = blockIdx.x * 256 + threadIdx.x;
    if (e >= n_edge) return;
    const int* ep = edges + (size_t)e * 6;
    int2 i01 = *reinterpret_cast<const int2*>(ep);
    int2 i23 = *reinterpret_cast<const int2*>(ep + 2);
    int2 i45 = *reinterpret_cast<const int2*>(ep + 4);
    g_estage[e] = make_int4(i01.x, i23.x, i45.x, i45.y);
    atomicAdd(&g_hist[i45.y], 1);
}

// ---------------------------------------------------------------------------
// K2b/c/d: exclusive scan of g_hist -> g_off (+cursor copy)
// ---------------------------------------------------------------------------
__global__ void __launch_bounds__(SCAN_TPB)
k_scan_block(int n)
{
    __shared__ int wsum[8];
    const int tid  = threadIdx.x;
    const int base = blockIdx.x * SCAN_CHUNK + tid * SCAN_EPT;

    int v[SCAN_EPT];
    int s = 0;
    #pragma unroll
    for (int i = 0; i < SCAN_EPT; i++) {
        int idx = base + i;
        v[i] = (idx < n) ? g_hist[idx] : 0;
        s += v[i];
    }
    const int lane = tid & 31, wid = tid >> 5;
    int inc = s;
    #pragma unroll
    for (int off_ = 1; off_ < 32; off_ <<= 1) {
        int t = __shfl_up_sync(0xFFFFFFFFu, inc, off_);
        if (lane >= off_) inc += t;
    }
    if (lane == 31) wsum[wid] = inc;
    __syncthreads();
    if (wid == 0) {
        int ws = (lane < 8) ? wsum[lane] : 0;
        #pragma unroll
        for (int off_ = 1; off_ < 8; off_ <<= 1) {
            int t = __shfl_up_sync(0xFFFFFFFFu, ws, off_);
            if (lane >= off_) ws += t;
        }
        if (lane < 8) wsum[lane] = ws;
    }
    __syncthreads();
    int run = inc - s + (wid > 0 ? wsum[wid - 1] : 0);
    #pragma unroll
    for (int i = 0; i < SCAN_EPT; i++) {
        int idx = base + i;
        if (idx < n) g_off[idx] = run;
        run += v[i];
    }
    if (tid == SCAN_TPB - 1) g_bsum[blockIdx.x] = run;
}

__global__ void k_scan_top(int nb)
{
    __shared__ int sh[NB_MAX];
    int t = threadIdx.x;
    int v = (t < nb) ? g_bsum[t] : 0;
    sh[t] = v;
    __syncthreads();
    #pragma unroll
    for (int off = 1; off < NB_MAX; off <<= 1) {
        int a = (t >= off) ? sh[t - off] : 0;
        __syncthreads();
        sh[t] += a;
        __syncthreads();
    }
    if (t < nb) g_bsum[t] = sh[t] - v;
}

__global__ void k_scan_add(int n, int n_edge)
{
    int i = blockIdx.x * 256 + threadIdx.x;
    if (i < n) {
        int o = g_off[i] + g_bsum[i >> 12];
        g_off[i]    = o;
        g_cursor[i] = o;
    }
    if (i == n) g_off[n] = n_edge;
}

// ---------------------------------------------------------------------------
// K2e: scatter staged edges into obj-grouped packed records + inline alpha
// ---------------------------------------------------------------------------
__global__ void __launch_bounds__(256)
k_scatter(const float* __restrict__ wa, const float* __restrict__ wab,
          int n_edge)
{
    int e = blockIdx.x * 256 + threadIdx.x;
    if (e >= n_edge) return;
    const int4 st = g_estage[e];        // (r_idx, rel, sub, obj)
    const int r_idx = st.x, rel = st.y, sub = st.z, obj = st.w;

    int pos = atomicAdd(&g_cursor[obj], 1);

    const float4 h4 = *reinterpret_cast<const float4*>(g_h5 + (size_t)sub * 8);
    const float  h5 = g_h5[(size_t)sub * 8 + 4];
    const float4 c4 = *reinterpret_cast<const float4*>(g_crel + rel * 8);
    const float  c5 = g_crel[rel * 8 + 4];
    const float4 q4 = *reinterpret_cast<const float4*>(g_cq + r_idx * 8);
    const float  q5 = g_cq[r_idx * 8 + 4];

    float z = __ldg(wab);
    z += fmaxf(h4.x + c4.x + q4.x, 0.f) * __ldg(wa + 0);
    z += fmaxf(h4.y + c4.y + q4.y, 0.f) * __ldg(wa + 1);
    z += fmaxf(h4.z + c4.z + q4.z, 0.f) * __ldg(wa + 2);
    z += fmaxf(h4.w + c4.w + q4.w, 0.f) * __ldg(wa + 3);
    z += fmaxf(h5   + c5   + q5,   0.f) * __ldg(wa + 4);
    const float alpha = 1.f / (1.f + expf(-z));

    g_epack[pos] = make_int4(sub, rel, obj, __float_as_int(alpha));
}

// ---------------------------------------------------------------------------
// K_MEGA (cooperative): edge2 -> score/max -> expsum -> taccum, grid.sync'd.
// Phase bodies identical to the Round-14 kernels, grid-stride form.
// ---------------------------------------------------------------------------
__global__ void __launch_bounds__(256)
k_mega(const float* __restrict__ hidden,
       const float* __restrict__ rela,
       const float* __restrict__ attn_b,
       int n_node, int n_edge)
{
    cg::grid_group grid = cg::this_grid();
    __shared__ float red[8];

    const int tid   = threadIdx.x;
    const int lane  = tid & 31;
    const int wid   = tid >> 5;
    const int gsize = gridDim.x * blockDim.x;
    const int gtid  = blockIdx.x * blockDim.x + tid;

    // ---- P1: segment max + s0/s1 (warp per node) ----
    {
        const float v0a = g_Mext[(2 * lane)     * 66 + 64];
        const float v1a = g_Mext[(2 * lane)     * 66 + 65];
        const float v0b = g_Mext[(2 * lane + 1) * 66 + 64];
        const float v1b = g_Mext[(2 * lane + 1) * 66 + 65];

        const int warps_total = gridDim.x * (blockDim.x >> 5);
        int w = blockIdx.x * (blockDim.x >> 5) + wid;

        for (int node = w; node < n_node; node += warps_total) {
            const int start = g_off[node];
            const int end   = g_off[node + 1];

            float m0 = -FLT_MAX, m1 = -FLT_MAX;
            for (int i = start; i < end; i++) {
                const int4 p = g_epack[i];
                const float alpha = __int_as_float(p.w);
                const float2 hs = *reinterpret_cast<const float2*>(
                    hidden + (size_t)p.x * 64 + 2 * lane);
                const float2 hr = *reinterpret_cast<const float2*>(
                    rela + (size_t)p.y * 64 + 2 * lane);
                m0 = fmaxf(m0, alpha * (hs.x - hr.x));
                m1 = fmaxf(m1, alpha * (hs.y - hr.y));
            }
            float2 o = (end > start) ? make_float2(m0, m1) : make_float2(0.f, 0.f);
            *reinterpret_cast<float2*>(g_agg + (size_t)node * 64 + 2 * lane) = o;

            float s0p = o.x * v0a + o.y * v0b;
            float s1p = o.x * v1a + o.y * v1b;
            #pragma unroll
            for (int off = 16; off > 0; off >>= 1) {
                s0p += __shfl_xor_sync(0xFFFFFFFFu, s0p, off);
                s1p += __shfl_xor_sync(0xFFFFFFFFu, s1p, off);
            }
            if (lane == 0) {
                g_s0[node] = s0p;
                g_s1[node] = s1p;
            }
        }
    }
    grid.sync();

    // ---- P2: scores + global max ----
    {
        const float ab = __ldg(attn_b);
        float mloc = -FLT_MAX;
        for (int e = gtid; e < n_edge; e += gsize) {
            const int4 p = g_epack[e];
            float s = g_s0[p.x] + g_s1[p.z] + ab;
            float sc = (s > 0.f) ? s : 0.2f * s;
            g_scores[e] = sc;
            mloc = fmaxf(mloc, sc);
        }
        #pragma unroll
        for (int off = 16; off > 0; off >>= 1)
            mloc = fmaxf(mloc, __shfl_xor_sync(0xFFFFFFFFu, mloc, off));
        if (lane == 0) red[wid] = mloc;
        __syncthreads();
        if (wid == 0) {
            float v = (lane < 8) ? red[lane] : -FLT_MAX;
            #pragma unroll
            for (int off = 4; off > 0; off >>= 1)
                v = fmaxf(v, __shfl_xor_sync(0xFFFFFFFFu, v, off));
            if (lane == 0) atomicMax(&g_max_enc, encf(v));
        }
    }
    grid.sync();

    // ---- P3: sum of exp(score - max) ----
    {
        const float gm = decf(g_max_enc);
        float sloc = 0.f;
        for (int e = gtid; e < n_edge; e += gsize)
            sloc += expf(g_scores[e] - gm);
        #pragma unroll
        for (int off = 16; off > 0; off >>= 1)
            sloc += __shfl_xor_sync(0xFFFFFFFFu, sloc, off);
        __syncthreads();              // red[] reuse hazard vs P2
        if (lane == 0) red[wid] = sloc;
        __syncthreads();
        if (wid == 0) {
            float s = (lane < 8) ? red[lane] : 0.f;
            #pragma unroll
            for (int off = 4; off > 0; off >>= 1)
                s += __shfl_xor_sync(0xFFFFFFFFu, s, off);
            if (lane == 0) atomicAdd(&g_sum, s);
        }
    }
    grid.sync();

    // ---- P4: t/wsum accumulation (16 lanes per edge) ----
    {
        const float inv = 1.f / g_sum;
        const float gm  = decf(g_max_enc);
        const long long total = (long long)n_edge * 16;
        for (long long t = gtid; t < total; t += gsize) {
            const int e = (int)(t >> 4);
            const int q = (int)(t & 15);
            const int4 p = g_epack[e];
            const float wgt = expf(__ldg(g_scores + e) - gm) * inv;
            const float4 m = *reinterpret_cast<const float4*>(
                g_agg + (size_t)p.z * 64 + q * 4);
            float* op = g_t + (size_t)p.x * 64 + q * 4;
            asm volatile("red.global.add.v4.f32 [%0], {%1, %2, %3, %4};"
                         :: "l"(op), "f"(wgt * m.x), "f"(wgt * m.y),
                            "f"(wgt * m.z), "f"(wgt * m.w)
                         : "memory");
            if (q == 0)
                asm volatile("red.global.add.f32 [%0], %1;"
                             :: "l"(g_wsum + p.x), "f"(wgt) : "memory");
        }
    }
}

// ---------------------------------------------------------------------------
// K8: final GEMM — out = t@M + wsum*b; plain coalesced stores, all rows.
// ---------------------------------------------------------------------------
#define AS_STRIDE 68
#define GEMM_ROWS 256
#define GEMM_SMEM ((GEMM_ROWS * AS_STRIDE + 64 * 64) * 4)

__global__ void __launch_bounds__(256, 2)
k_gemm(int n_node, const float* __restrict__ Wnode_b, float* __restrict__ out)
{
    extern __shared__ float smem[];
    float* As  = smem;                            // 256 * 68
    float* MsL = smem + GEMM_ROWS * AS_STRIDE;    // 64 * 64, [k][half][tx][4]

    const int tid = threadIdx.x;
    for (int i = tid; i < 64 * 64; i += 256) {
        int k = i >> 6, c = i & 63;
        MsL[k * 64 + ((c & 4) ? 32 : 0) + (c >> 3) * 4 + (c & 3)] =
            g_Mext[k * 66 + c];
    }

    const int rb = blockIdx.x * GEMM_ROWS;
    const float4* src = reinterpret_cast<const float4*>(g_t + (size_t)rb * 64);
    const bool full = (rb + GEMM_ROWS <= n_node);

    #pragma unroll
    for (int t = 0; t < 16; t++) {
        int vidx = tid + t * 256;
        int r  = vidx >> 4;
        int k4 = (vidx & 15) * 4;
        float4 u = make_float4(0.f, 0.f, 0.f, 0.f);
        if (full || rb + r < n_node) u = src[vidx];
        *reinterpret_cast<float4*>(As + r * AS_STRIDE + k4) = u;
    }
    __syncthreads();

    const int tx = tid & 7;
    const int ty = tid >> 3;

    unsigned long long acc[8][4];
    #pragma unroll
    for (int i = 0; i < 8; i++)
        #pragma unroll
        for (int c = 0; c < 4; c++) acc[i][c] = 0ull;

    const float* arow  = As + ty * 8 * AS_STRIDE;
    const float* mbase = MsL + tx * 4;

    for (int k4 = 0; k4 < 64; k4 += 4) {
        float4 a[8];
        #pragma unroll
        for (int i = 0; i < 8; i++)
            a[i] = *reinterpret_cast<const float4*>(arow + i * AS_STRIDE + k4);

        #pragma unroll
        for (int kk = 0; kk < 4; kk++) {
            const ulonglong2 mp0 = *reinterpret_cast<const ulonglong2*>(mbase + (k4 + kk) * 64);
            const ulonglong2 mp1 = *reinterpret_cast<const ulonglong2*>(mbase + (k4 + kk) * 64 + 32);
            #pragma unroll
            for (int i = 0; i < 8; i++) {
                const float av = (kk == 0) ? a[i].x : (kk == 1) ? a[i].y
                               : (kk == 2) ? a[i].z : a[i].w;
                const unsigned long long aa = pack2(av);
                ffma2(acc[i][0], aa, mp0.x);
                ffma2(acc[i][1], aa, mp0.y);
                ffma2(acc[i][2], aa, mp1.x);
                ffma2(acc[i][3], aa, mp1.y);
            }
        }
    }

    const float4 b0 = *reinterpret_cast<const float4*>(Wnode_b + tx * 8);
    const float4 b1 = *reinterpret_cast<const float4*>(Wnode_b + tx * 8 + 4);
    #pragma unroll
    for (int i = 0; i < 8; i++) {
        int grow = rb + ty * 8 + i;
        if (grow < n_node) {
            const float ws = g_wsum[grow];
            float2 a0 = unpack2(acc[i][0]);
            float2 a1 = unpack2(acc[i][1]);
            float2 a2 = unpack2(acc[i][2]);
            float2 a3 = unpack2(acc[i][3]);
            float* op = out + (size_t)grow * 64 + tx * 8;
            *reinterpret_cast<float4*>(op) =
                make_float4(a0.x + ws * b0.x, a0.y + ws * b0.y,
                            a1.x + ws * b0.z, a1.y + ws * b0.w);
            *reinterpret_cast<float4*>(op + 4) =
                make_float4(a2.x + ws * b1.x, a2.y + ws * b1.y,
                            a3.x + ws * b1.z, a3.y + ws * b1.w);
        }
    }
}

// ---------------------------------------------------------------------------
// kernel_launch
// ---------------------------------------------------------------------------
extern "C" void kernel_launch(void* const* d_in, const int* in_sizes, int n_in,
                              void* d_out, int out_size)
{
    const float* hidden    = (const float*)d_in[0];
    const float* rela      = (const float*)d_in[1];
    const float* Ws        = (const float*)d_in[2];
    const float* Wr        = (const float*)d_in[3];
    const float* Wqr_w     = (const float*)d_in[4];
    const float* Wqr_b     = (const float*)d_in[5];
    const float* walpha_w  = (const float*)d_in[6];
    const float* walpha_b  = (const float*)d_in[7];
    const float* Wh        = (const float*)d_in[8];
    const float* attn_fc_w = (const float*)d_in[9];
    const float* attn_fc_b = (const float*)d_in[10];
    const float* Wnode_w   = (const float*)d_in[11];
    const float* Wnode_b   = (const float*)d_in[12];
    const int*   q_rel     = (const int*)d_in[14];
    const int*   edges     = (const int*)d_in[15];
    float*       out       = (float*)d_out;

    int n_edge = in_sizes[15] / 6;
    int n_node = in_sizes[16] / 2;
    int nrel   = in_sizes[1] / 64;
    int batch  = in_sizes[14];
    const int nb = (n_node + SCAN_CHUNK - 1) / SCAN_CHUNK;

    static int coop_grid = 0;
    if (coop_grid == 0) {
        cudaFuncSetAttribute(k_gemm, cudaFuncAttributeMaxDynamicSharedMemorySize,
                             GEMM_SMEM);
        int bpm = 0, nsm = 0;
        cudaOccupancyMaxActiveBlocksPerMultiprocessor(&bpm, k_mega, 256, 0);
        cudaDeviceGetAttribute(&nsm, cudaDevAttrMultiProcessorCount, 0);
        coop_grid = bpm * nsm;
        if (coop_grid <= 0) coop_grid = 592;   // conservative fallback
    }

    // fused setup + h5 + init
    k_prep<<<PREP_BLKS, 256>>>(Wh, Wnode_w, attn_fc_w, rela, Wr, Wqr_w, Wqr_b,
                               q_rel, hidden, Ws, nrel, batch, n_node);

    // counting sort by obj
    k_hist<<<(n_edge + 255) / 256, 256>>>(edges, n_edge);
    k_scan_block<<<nb, SCAN_TPB>>>(n_node);
    k_scan_top<<<1, NB_MAX>>>(nb);
    k_scan_add<<<(n_node + 256) / 256, 256>>>(n_node, n_edge);
    k_scatter<<<(n_edge + 255) / 256, 256>>>(walpha_w, walpha_b, n_edge);

    // fused edge2 + score + sum + taccum (cooperative, grid.sync'd)
    {
        void* args[] = { (void*)&hidden, (void*)&rela, (void*)&attn_fc_b,
                         (void*)&n_node, (void*)&n_edge };
        cudaLaunchCooperativeKernel((void*)k_mega, dim3(coop_grid), dim3(256),
                                    args, 0, 0);
    }

    // final GEMM: out = t@M + wsum*b
    k_gemm<<<(n_node + GEMM_ROWS - 1) / GEMM_ROWS, 256, GEMM_SMEM>>>(
        n_node, Wnode_b, out);
}

// round 16
// speedup vs baseline: 1.0630x; 1.0630x over previous
#include <cuda_runtime.h>
#include <cfloat>
#include <cstdint>

// ---------------------------------------------------------------------------
// Problem-size constants
// ---------------------------------------------------------------------------
#define N_NODE_MAX 500000
#define N_EDGE_MAX 1000000
#define NREL_MAX   512
#define BATCH_MAX  64

#define SCAN_TPB   256
#define SCAN_EPT   16
#define SCAN_CHUNK 4096
#define NB_MAX     128

// k_prep block partitions
#define PREP_SETUP_BLKS 32
#define PREP_H5_BLKS    2368
#define PREP_INIT_BLKS  1696
#define PREP_BLKS (PREP_SETUP_BLKS + PREP_H5_BLKS + PREP_INIT_BLKS)

// ---------------------------------------------------------------------------
// Device scratch
// ---------------------------------------------------------------------------
__device__ float    g_agg[(size_t)N_NODE_MAX * 64];      // segment-max result
__device__ float    g_t[(size_t)N_NODE_MAX * 64];        // sum_e w_e * agg[obj_e]
__device__ float    g_wsum[N_NODE_MAX];                  // sum_e w_e (per sub)
__device__ float    g_h5[(size_t)N_NODE_MAX * 8];        // hidden@Ws (padded)
__device__ float    g_s0[N_NODE_MAX];
__device__ float    g_s1[N_NODE_MAX];
__device__ float    g_scores[N_EDGE_MAX];
__device__ float    g_Mext[64 * 66];                     // [k][c]: c<64 M, 64 v0, 65 v1
__device__ float    g_crel[NREL_MAX * 8];
__device__ float    g_cq[BATCH_MAX * 8];
__device__ unsigned g_max_enc;
__device__ float    g_sum;

// edge staging (original order) + sorted packed records
__device__ int4     g_estage[N_EDGE_MAX];   // (r_idx, rel, sub, obj)
__device__ int4     g_epack[N_EDGE_MAX];    // (sub, rel, obj, alpha_bits), obj-sorted

// counting-sort scratch (by obj)
__device__ int      g_hist[N_NODE_MAX];
__device__ int      g_off[N_NODE_MAX + 1];
__device__ int      g_cursor[N_NODE_MAX];
__device__ int      g_bsum[NB_MAX];

// ---------------------------------------------------------------------------
// Order-preserving float <-> uint encoding
// ---------------------------------------------------------------------------
__device__ __forceinline__ unsigned encf(float x) {
    unsigned u = __float_as_uint(x);
    return (u & 0x80000000u) ? ~u : (u | 0x80000000u);
}
__device__ __forceinline__ float decf(unsigned u) {
    return (u & 0x80000000u) ? __uint_as_float(u & 0x7FFFFFFFu)
                             : __uint_as_float(~u);
}

// ---------------------------------------------------------------------------
// Packed f32x2 helpers
// ---------------------------------------------------------------------------
__device__ __forceinline__ unsigned long long pack2(float a) {
    unsigned long long r;
    asm("mov.b64 %0, {%1, %1};" : "=l"(r) : "r"(__float_as_uint(a)));
    return r;
}
__device__ __forceinline__ void ffma2(unsigned long long& d,
                                      unsigned long long a,
                                      unsigned long long b) {
    asm("fma.rn.f32x2 %0, %1, %2, %0;" : "+l"(d) : "l"(a), "l"(b));
}
__device__ __forceinline__ float2 unpack2(unsigned long long v) {
    unsigned lo, hi;
    asm("mov.b64 {%0, %1}, %2;" : "=r"(lo), "=r"(hi) : "l"(v));
    return make_float2(__uint_as_float(lo), __uint_as_float(hi));
}

// ---------------------------------------------------------------------------
// K_PREP: fused setup + h5 + init (independent work, blockIdx-partitioned,
//         no internal synchronization — scheduling-neutral fusion)
// ---------------------------------------------------------------------------
__global__ void __launch_bounds__(256)
k_prep(const float* __restrict__ Wh,
       const float* __restrict__ Wnode,
       const float* __restrict__ attn_w,
       const float* __restrict__ rela,
       const float* __restrict__ Wr,
       const float* __restrict__ Wqr_w,
       const float* __restrict__ Wqr_b,
       const int*   __restrict__ q_rel,
       const float* __restrict__ hidden,
       const float* __restrict__ Ws,
       int nrel, int batch, int n_node)
{
    const int b = blockIdx.x;

    if (b < PREP_SETUP_BLKS) {
        // --- setup tables ---
        int gtid   = b * blockDim.x + threadIdx.x;
        int stride = PREP_SETUP_BLKS * blockDim.x;

        for (int i = gtid; i < 64 * 66; i += stride) {
            int k = i / 66, c = i % 66;
            float s = 0.f;
            if (c < 64) {
                #pragma unroll 8
                for (int j = 0; j < 64; j++) s += Wh[k * 64 + j] * Wnode[j * 64 + c];
            } else {
                const float* w = attn_w + (c - 64) * 64;
                #pragma unroll 8
                for (int j = 0; j < 64; j++) s += Wh[k * 64 + j] * w[j];
            }
            g_Mext[i] = s;
        }
        for (int i = gtid; i < nrel * 5; i += stride) {
            int r = i / 5, j = i % 5;
            float s = 0.f;
            #pragma unroll 8
            for (int k = 0; k < 64; k++) s += rela[r * 64 + k] * Wr[k * 5 + j];
            g_crel[r * 8 + j] = s;
        }
        for (int i = gtid; i < batch * 5; i += stride) {
            int bb = i / 5, j = i % 5;
            int qr = q_rel[bb];
            float s = Wqr_b[j];
            #pragma unroll 8
            for (int k = 0; k < 64; k++) s += rela[qr * 64 + k] * Wqr_w[k * 5 + j];
            g_cq[bb * 8 + j] = s;
        }
        if (gtid == 0) { g_max_enc = 0u; g_sum = 0.f; }
    } else if (b < PREP_SETUP_BLKS + PREP_H5_BLKS) {
        // --- H5 = hidden @ Ws (warp per node) ---
        const int lane = threadIdx.x & 31;
        float wsa[5], wsb[5];
        #pragma unroll
        for (int j = 0; j < 5; j++) {
            wsa[j] = __ldg(Ws + (2 * lane) * 5 + j);
            wsb[j] = __ldg(Ws + (2 * lane + 1) * 5 + j);
        }
        const int warps_total = PREP_H5_BLKS * (blockDim.x >> 5);
        int w = (b - PREP_SETUP_BLKS) * (blockDim.x >> 5) + (threadIdx.x >> 5);

        for (int node = w; node < n_node; node += warps_total) {
            const float2 h = *reinterpret_cast<const float2*>(
                hidden + (size_t)node * 64 + 2 * lane);
            float p0 = h.x * wsa[0] + h.y * wsb[0];
            float p1 = h.x * wsa[1] + h.y * wsb[1];
            float p2 = h.x * wsa[2] + h.y * wsb[2];
            float p3 = h.x * wsa[3] + h.y * wsb[3];
            float p4 = h.x * wsa[4] + h.y * wsb[4];
            #pragma unroll
            for (int off = 16; off > 0; off >>= 1) {
                p0 += __shfl_xor_sync(0xFFFFFFFFu, p0, off);
                p1 += __shfl_xor_sync(0xFFFFFFFFu, p1, off);
                p2 += __shfl_xor_sync(0xFFFFFFFFu, p2, off);
                p3 += __shfl_xor_sync(0xFFFFFFFFu, p3, off);
                p4 += __shfl_xor_sync(0xFFFFFFFFu, p4, off);
            }
            if (lane == 0) {
                float* dst = g_h5 + (size_t)node * 8;
                *reinterpret_cast<float4*>(dst) = make_float4(p0, p1, p2, p3);
                dst[4] = p4;
            }
        }
    } else {
        // --- init zeros: t, wsum, hist ---
        size_t gtid   = (size_t)(b - PREP_SETUP_BLKS - PREP_H5_BLKS) * blockDim.x
                        + threadIdx.x;
        size_t stride = (size_t)PREP_INIT_BLKS * blockDim.x;

        float4* tp = reinterpret_cast<float4*>(g_t);
        size_t  nt = (size_t)n_node * 16;
        float4  zv = make_float4(0.f, 0.f, 0.f, 0.f);
        for (size_t t = gtid; t < nt; t += stride) tp[t] = zv;
        for (size_t t = gtid; t < (size_t)n_node; t += stride) {
            g_hist[t] = 0;
            g_wsum[t] = 0.f;
        }
    }
}

// ---------------------------------------------------------------------------
// K2a: histogram over obj + stage compact edge tuples
// ---------------------------------------------------------------------------
__global__ void __launch_bounds__(256)
k_hist(const int* __restrict__ edges, int n_edge)
{
    int e = blockIdx.x * 256 + threadIdx.x;
    if (e >= n_edge) return;
    const int* ep = edges + (size_t)e * 6;
    int2 i01 = *reinterpret_cast<const int2*>(ep);
    int2 i23 = *reinterpret_cast<const int2*>(ep + 2);
    int2 i45 = *reinterpret_cast<const int2*>(ep + 4);
    g_estage[e] = make_int4(i01.x, i23.x, i45.x, i45.y);
    atomicAdd(&g_hist[i45.y], 1);
}

// ---------------------------------------------------------------------------
// K2b/c/d: exclusive scan of g_hist -> g_off (+cursor copy)
// ---------------------------------------------------------------------------
__global__ void __launch_bounds__(SCAN_TPB)
k_scan_block(int n)
{
    __shared__ int wsum[8];
    const int tid  = threadIdx.x;
    const int base = blockIdx.x * SCAN_CHUNK + tid * SCAN_EPT;

    int v[SCAN_EPT];
    int s = 0;
    #pragma unroll
    for (int i = 0; i < SCAN_EPT; i++) {
        int idx = base + i;
        v[i] = (idx < n) ? g_hist[idx] : 0;
        s += v[i];
    }
    const int lane = tid & 31, wid = tid >> 5;
    int inc = s;
    #pragma unroll
    for (int off_ = 1; off_ < 32; off_ <<= 1) {
        int t = __shfl_up_sync(0xFFFFFFFFu, inc, off_);
        if (lane >= off_) inc += t;
    }
    if (lane == 31) wsum[wid] = inc;
    __syncthreads();
    if (wid == 0) {
        int ws = (lane < 8) ? wsum[lane] : 0;
        #pragma unroll
        for (int off_ = 1; off_ < 8; off_ <<= 1) {
            int t = __shfl_up_sync(0xFFFFFFFFu, ws, off_);
            if (lane >= off_) ws += t;
        }
        if (lane < 8) wsum[lane] = ws;
    }
    __syncthreads();
    int run = inc - s + (wid > 0 ? wsum[wid - 1] : 0);
    #pragma unroll
    for (int i = 0; i < SCAN_EPT; i++) {
        int idx = base + i;
        if (idx < n) g_off[idx] = run;
        run += v[i];
    }
    if (tid == SCAN_TPB - 1) g_bsum[blockIdx.x] = run;
}

__global__ void k_scan_top(int nb)
{
    __shared__ int sh[NB_MAX];
    int t = threadIdx.x;
    int v = (t < nb) ? g_bsum[t] : 0;
    sh[t] = v;
    __syncthreads();
    #pragma unroll
    for (int off = 1; off < NB_MAX; off <<= 1) {
        int a = (t >= off) ? sh[t - off] : 0;
        __syncthreads();
        sh[t] += a;
        __syncthreads();
    }
    if (t < nb) g_bsum[t] = sh[t] - v;
}

__global__ void k_scan_add(int n, int n_edge)
{
    int i = blockIdx.x * 256 + threadIdx.x;
    if (i < n) {
        int o = g_off[i] + g_bsum[i >> 12];
        g_off[i]    = o;
        g_cursor[i] = o;
    }
    if (i == n) g_off[n] = n_edge;
}

// ---------------------------------------------------------------------------
// K2e: scatter staged edges into obj-grouped packed records + inline alpha
// ---------------------------------------------------------------------------
__global__ void __launch_bounds__(256)
k_scatter(const float* __restrict__ wa, const float* __restrict__ wab,
          int n_edge)
{
    int e = blockIdx.x * 256 + threadIdx.x;
    if (e >= n_edge) return;
    const int4 st = g_estage[e];        // (r_idx, rel, sub, obj)
    const int r_idx = st.x, rel = st.y, sub = st.z, obj = st.w;

    int pos = atomicAdd(&g_cursor[obj], 1);

    const float4 h4 = *reinterpret_cast<const float4*>(g_h5 + (size_t)sub * 8);
    const float  h5 = g_h5[(size_t)sub * 8 + 4];
    const float4 c4 = *reinterpret_cast<const float4*>(g_crel + rel * 8);
    const float  c5 = g_crel[rel * 8 + 4];
    const float4 q4 = *reinterpret_cast<const float4*>(g_cq + r_idx * 8);
    const float  q5 = g_cq[r_idx * 8 + 4];

    float z = __ldg(wab);
    z += fmaxf(h4.x + c4.x + q4.x, 0.f) * __ldg(wa + 0);
    z += fmaxf(h4.y + c4.y + q4.y, 0.f) * __ldg(wa + 1);
    z += fmaxf(h4.z + c4.z + q4.z, 0.f) * __ldg(wa + 2);
    z += fmaxf(h4.w + c4.w + q4.w, 0.f) * __ldg(wa + 3);
    z += fmaxf(h5   + c5   + q5,   0.f) * __ldg(wa + 4);
    const float alpha = 1.f / (1.f + expf(-z));

    g_epack[pos] = make_int4(sub, rel, obj, __float_as_int(alpha));
}

// ---------------------------------------------------------------------------
// K3c: segment max — warp per node, serial edge walk; s0/s1 epilogue
// ---------------------------------------------------------------------------
__global__ void __launch_bounds__(256)
k_edge2(const float* __restrict__ hidden,
        const float* __restrict__ rela,
        int n_node)
{
    const int lane = threadIdx.x & 31;

    const float v0a = g_Mext[(2 * lane)     * 66 + 64];
    const float v1a = g_Mext[(2 * lane)     * 66 + 65];
    const float v0b = g_Mext[(2 * lane + 1) * 66 + 64];
    const float v1b = g_Mext[(2 * lane + 1) * 66 + 65];

    const int warps_total = gridDim.x * (blockDim.x >> 5);
    int w = blockIdx.x * (blockDim.x >> 5) + (threadIdx.x >> 5);

    for (int node = w; node < n_node; node += warps_total) {
        const int start = g_off[node];
        const int end   = g_off[node + 1];

        float m0 = -FLT_MAX, m1 = -FLT_MAX;
        for (int i = start; i < end; i++) {
            const int4 p = g_epack[i];                 // broadcast LDG.128
            const int   sub   = p.x;
            const int   rel   = p.y;
            const float alpha = __int_as_float(p.w);
            const float2 hs = *reinterpret_cast<const float2*>(hidden + (size_t)sub * 64 + 2 * lane);
            const float2 hr = *reinterpret_cast<const float2*>(rela   + (size_t)rel * 64 + 2 * lane);
            m0 = fmaxf(m0, alpha * (hs.x - hr.x));
            m1 = fmaxf(m1, alpha * (hs.y - hr.y));
        }
        float2 o = (end > start) ? make_float2(m0, m1) : make_float2(0.f, 0.f);
        *reinterpret_cast<float2*>(g_agg + (size_t)node * 64 + 2 * lane) = o;

        float s0p = o.x * v0a + o.y * v0b;
        float s1p = o.x * v1a + o.y * v1b;
        #pragma unroll
        for (int off = 16; off > 0; off >>= 1) {
            s0p += __shfl_xor_sync(0xFFFFFFFFu, s0p, off);
            s1p += __shfl_xor_sync(0xFFFFFFFFu, s1p, off);
        }
        if (lane == 0) {
            g_s0[node] = s0p;
            g_s1[node] = s1p;
        }
    }
}

// ---------------------------------------------------------------------------
// K5: edge scores + global max (raw scores stored; exp NOT materialized)
// ---------------------------------------------------------------------------
__global__ void __launch_bounds__(256)
k_score(const float* __restrict__ attn_b, int n_edge)
{
    const int e = blockIdx.x * 256 + threadIdx.x;
    float sc = -FLT_MAX;
    if (e < n_edge) {
        const int4 p = g_epack[e];
        float s = g_s0[p.x] + g_s1[p.z] + __ldg(attn_b);
        sc = (s > 0.f) ? s : 0.2f * s;
        g_scores[e] = sc;
    }
    __shared__ float red[8];
    const int lane = threadIdx.x & 31, wid = threadIdx.x >> 5;
    #pragma unroll
    for (int off = 16; off > 0; off >>= 1)
        sc = fmaxf(sc, __shfl_xor_sync(0xFFFFFFFFu, sc, off));
    if (lane == 0) red[wid] = sc;
    __syncthreads();
    if (wid == 0) {
        float v = (lane < 8) ? red[lane] : -FLT_MAX;
        #pragma unroll
        for (int off = 4; off > 0; off >>= 1)
            v = fmaxf(v, __shfl_xor_sync(0xFFFFFFFFu, v, off));
        if (lane == 0) atomicMax(&g_max_enc, encf(v));
    }
}

// ---------------------------------------------------------------------------
// K6: global sum of exp(score - max) — reduce only, no store
// ---------------------------------------------------------------------------
__global__ void __launch_bounds__(256)
k_sum(int n_edge)
{
    const float gm = decf(g_max_enc);
    const int e = blockIdx.x * 256 + threadIdx.x;
    float v = 0.f;
    if (e < n_edge) v = expf(g_scores[e] - gm);
    __shared__ float red[8];
    const int lane = threadIdx.x & 31, wid = threadIdx.x >> 5;
    #pragma unroll
    for (int off = 16; off > 0; off >>= 1)
        v += __shfl_xor_sync(0xFFFFFFFFu, v, off);
    if (lane == 0) red[wid] = v;
    __syncthreads();
    if (wid == 0) {
        float s = (lane < 8) ? red[lane] : 0.f;
        #pragma unroll
        for (int off = 4; off > 0; off >>= 1)
            s += __shfl_xor_sync(0xFFFFFFFFu, s, off);
        if (lane == 0) atomicAdd(&g_sum, s);
    }
}

// ---------------------------------------------------------------------------
// K7: t-accumulation — t[sub] += w_e * agg[obj]; wsum[sub] += w_e
//     16 threads per edge; w_e = exp(score-gm)/sum recomputed inline.
// ---------------------------------------------------------------------------
__global__ void __launch_bounds__(256)
k_taccum(int n_edge)
{
    const float inv = 1.f / g_sum;
    const float gm  = decf(g_max_enc);
    const int t = blockIdx.x * 256 + threadIdx.x;
    const int e = t >> 4;
    const int q = t & 15;
    if (e >= n_edge) return;

    const int4 p = g_epack[e];          // broadcast across the 16 lanes
    const int sub = p.x;
    const int obj = p.z;
    const float wgt = expf(__ldg(g_scores + e) - gm) * inv;
    const float4 m = *reinterpret_cast<const float4*>(
        g_agg + (size_t)obj * 64 + q * 4);
    float* op = g_t + (size_t)sub * 64 + q * 4;
    asm volatile("red.global.add.v4.f32 [%0], {%1, %2, %3, %4};"
                 :: "l"(op), "f"(wgt * m.x), "f"(wgt * m.y),
                    "f"(wgt * m.z), "f"(wgt * m.w)
                 : "memory");
    if (q == 0)
        asm volatile("red.global.add.f32 [%0], %1;"
                     :: "l"(g_wsum + sub), "f"(wgt) : "memory");
}

// ---------------------------------------------------------------------------
// K8: final GEMM — out = t@M + wsum*b; plain coalesced stores, all rows.
// ---------------------------------------------------------------------------
#define AS_STRIDE 68
#define GEMM_ROWS 256
#define GEMM_SMEM ((GEMM_ROWS * AS_STRIDE + 64 * 64) * 4)

__global__ void __launch_bounds__(256, 2)
k_gemm(int n_node, const float* __restrict__ Wnode_b, float* __restrict__ out)
{
    extern __shared__ float smem[];
    float* As  = smem;                            // 256 * 68
    float* MsL = smem + GEMM_ROWS * AS_STRIDE;    // 64 * 64, [k][half][tx][4]

    const int tid = threadIdx.x;
    for (int i = tid; i < 64 * 64; i += 256) {
        int k = i >> 6, c = i & 63;
        MsL[k * 64 + ((c & 4) ? 32 : 0) + (c >> 3) * 4 + (c & 3)] =
            g_Mext[k * 66 + c];
    }

    const int rb = blockIdx.x * GEMM_ROWS;
    const float4* src = reinterpret_cast<const float4*>(g_t + (size_t)rb * 64);
    const bool full = (rb + GEMM_ROWS <= n_node);

    #pragma unroll
    for (int t = 0; t < 16; t++) {
        int vidx = tid + t * 256;
        int r  = vidx >> 4;
        int k4 = (vidx & 15) * 4;
        float4 u = make_float4(0.f, 0.f, 0.f, 0.f);
        if (full || rb + r < n_node) u = src[vidx];
        *reinterpret_cast<float4*>(As + r * AS_STRIDE + k4) = u;
    }
    __syncthreads();

    const int tx = tid & 7;
    const int ty = tid >> 3;

    unsigned long long acc[8][4];
    #pragma unroll
    for (int i = 0; i < 8; i++)
        #pragma unroll
        for (int c = 0; c < 4; c++) acc[i][c] = 0ull;

    const float* arow  = As + ty * 8 * AS_STRIDE;
    const float* mbase = MsL + tx * 4;

    for (int k4 = 0; k4 < 64; k4 += 4) {
        float4 a[8];
        #pragma unroll
        for (int i = 0; i < 8; i++)
            a[i] = *reinterpret_cast<const float4*>(arow + i * AS_STRIDE + k4);

        #pragma unroll
        for (int kk = 0; kk < 4; kk++) {
            const ulonglong2 mp0 = *reinterpret_cast<const ulonglong2*>(mbase + (k4 + kk) * 64);
            const ulonglong2 mp1 = *reinterpret_cast<const ulonglong2*>(mbase + (k4 + kk) * 64 + 32);
            #pragma unroll
            for (int i = 0; i < 8; i++) {
                const float av = (kk == 0) ? a[i].x : (kk == 1) ? a[i].y
                               : (kk == 2) ? a[i].z : a[i].w;
                const unsigned long long aa = pack2(av);
                ffma2(acc[i][0], aa, mp0.x);
                ffma2(acc[i][1], aa, mp0.y);
                ffma2(acc[i][2], aa, mp1.x);
                ffma2(acc[i][3], aa, mp1.y);
            }
        }
    }

    const float4 b0 = *reinterpret_cast<const float4*>(Wnode_b + tx * 8);
    const float4 b1 = *reinterpret_cast<const float4*>(Wnode_b + tx * 8 + 4);
    #pragma unroll
    for (int i = 0; i < 8; i++) {
        int grow = rb + ty * 8 + i;
        if (grow < n_node) {
            const float ws = g_wsum[grow];
            float2 a0 = unpack2(acc[i][0]);
            float2 a1 = unpack2(acc[i][1]);
            float2 a2 = unpack2(acc[i][2]);
            float2 a3 = unpack2(acc[i][3]);
            float* op = out + (size_t)grow * 64 + tx * 8;
            *reinterpret_cast<float4*>(op) =
                make_float4(a0.x + ws * b0.x, a0.y + ws * b0.y,
                            a1.x + ws * b0.z, a1.y + ws * b0.w);
            *reinterpret_cast<float4*>(op + 4) =
                make_float4(a2.x + ws * b1.x, a2.y + ws * b1.y,
                            a3.x + ws * b1.z, a3.y + ws * b1.w);
        }
    }
}

// ---------------------------------------------------------------------------
// kernel_launch
// ---------------------------------------------------------------------------
extern "C" void kernel_launch(void* const* d_in, const int* in_sizes, int n_in,
                              void* d_out, int out_size)
{
    const float* hidden    = (const float*)d_in[0];
    const float* rela      = (const float*)d_in[1];
    const float* Ws        = (const float*)d_in[2];
    const float* Wr        = (const float*)d_in[3];
    const float* Wqr_w     = (const float*)d_in[4];
    const float* Wqr_b     = (const float*)d_in[5];
    const float* walpha_w  = (const float*)d_in[6];
    const float* walpha_b  = (const float*)d_in[7];
    const float* Wh        = (const float*)d_in[8];
    const float* attn_fc_w = (const float*)d_in[9];
    const float* attn_fc_b = (const float*)d_in[10];
    const float* Wnode_w   = (const float*)d_in[11];
    const float* Wnode_b   = (const float*)d_in[12];
    const int*   q_rel     = (const int*)d_in[14];
    const int*   edges     = (const int*)d_in[15];
    float*       out       = (float*)d_out;

    const int n_edge = in_sizes[15] / 6;
    const int n_node = in_sizes[16] / 2;
    const int nrel   = in_sizes[1] / 64;
    const int batch  = in_sizes[14];
    const int nb     = (n_node + SCAN_CHUNK - 1) / SCAN_CHUNK;

    static bool attr_set = false;
    if (!attr_set) {
        cudaFuncSetAttribute(k_gemm, cudaFuncAttributeMaxDynamicSharedMemorySize,
                             GEMM_SMEM);
        attr_set = true;
    }

    // fused setup + h5 + init (independent, blockIdx-partitioned)
    k_prep<<<PREP_BLKS, 256>>>(Wh, Wnode_w, attn_fc_w, rela, Wr, Wqr_w, Wqr_b,
                               q_rel, hidden, Ws, nrel, batch, n_node);

    // counting sort by obj (hist stages tuples; scatter computes alpha inline)
    k_hist<<<(n_edge + 255) / 256, 256>>>(edges, n_edge);
    k_scan_block<<<nb, SCAN_TPB>>>(n_node);
    k_scan_top<<<1, NB_MAX>>>(nb);
    k_scan_add<<<(n_node + 256) / 256, 256>>>(n_node, n_edge);
    k_scatter<<<(n_edge + 255) / 256, 256>>>(walpha_w, walpha_b, n_edge);

    // segment max + s0/s1 epilogue (warp per node)
    k_edge2<<<2368, 256>>>(hidden, rela, n_node);

    // softmax statistics (max, then sum; exp not materialized)
    k_score<<<(n_edge + 255) / 256, 256>>>(attn_fc_b, n_edge);
    k_sum<<<(n_edge + 255) / 256, 256>>>(n_edge);

    // t/wsum accumulation (16 threads/edge, RED.128, exp inline)
    k_taccum<<<(n_edge * 16 + 255) / 256, 256>>>(n_edge);

    // final GEMM: out = t@M + wsum*b (plain stores)
    k_gemm<<<(n_node + GEMM_ROWS - 1) / GEMM_ROWS, 256, GEMM_SMEM>>>(
        n_node, Wnode_b, out);
}

// round 17
// speedup vs baseline: 1.0804x; 1.0164x over previous
#include <cuda_runtime.h>
#include <cfloat>
#include <cstdint>

// ---------------------------------------------------------------------------
// Problem-size constants
// ---------------------------------------------------------------------------
#define N_NODE_MAX 500000
#define N_EDGE_MAX 1000000
#define NREL_MAX   512
#define BATCH_MAX  64

#define SCAN_TPB   256
#define SCAN_EPT   16
#define SCAN_CHUNK 4096
#define NB_MAX     128
#define SBLK_MAX   4096

// k_prep block partitions
#define PREP_SETUP_BLKS 32
#define PREP_H5_BLKS    2368
#define PREP_INIT_BLKS  1696
#define PREP_BLKS (PREP_SETUP_BLKS + PREP_H5_BLKS + PREP_INIT_BLKS)

// ---------------------------------------------------------------------------
// Device scratch
// ---------------------------------------------------------------------------
__device__ float    g_agg[(size_t)N_NODE_MAX * 64];      // segment-max result
__device__ float    g_t[(size_t)N_NODE_MAX * 64];        // sum_e w_e * agg[obj_e]
__device__ float    g_wsum[N_NODE_MAX];                  // sum_e w_e (per sub)
__device__ float    g_h5[(size_t)N_NODE_MAX * 8];        // hidden@Ws (padded)
__device__ float    g_s0[N_NODE_MAX];
__device__ float    g_s1[N_NODE_MAX];
__device__ float    g_scores[N_EDGE_MAX];
__device__ float    g_Mext[64 * 66];                     // [k][c]: c<64 M, 64 v0, 65 v1
__device__ float    g_crel[NREL_MAX * 8];
__device__ float    g_cq[BATCH_MAX * 8];
__device__ unsigned g_max_enc;
__device__ float    g_sum;

// edge staging (original order) + sorted packed records
__device__ int4     g_estage[N_EDGE_MAX];   // (r_idx, rel, sub, obj)
__device__ int4     g_epack[N_EDGE_MAX];    // (sub, rel, obj, alpha_bits), obj-sorted

// counting-sort scratch (by obj)
__device__ int      g_hist[N_NODE_MAX];
__device__ int      g_off[N_NODE_MAX + 1];
__device__ int      g_cursor[N_NODE_MAX];
__device__ unsigned long long g_sstate[NB_MAX];  // lookback: (status<<32)|value

// online-softmax block partials
__device__ float    g_bmax[SBLK_MAX];
__device__ float    g_bsum[SBLK_MAX];

// ---------------------------------------------------------------------------
// Order-preserving float <-> uint encoding
// ---------------------------------------------------------------------------
__device__ __forceinline__ unsigned encf(float x) {
    unsigned u = __float_as_uint(x);
    return (u & 0x80000000u) ? ~u : (u | 0x80000000u);
}
__device__ __forceinline__ float decf(unsigned u) {
    return (u & 0x80000000u) ? __uint_as_float(u & 0x7FFFFFFFu)
                             : __uint_as_float(~u);
}

// ---------------------------------------------------------------------------
// Packed f32x2 helpers
// ---------------------------------------------------------------------------
__device__ __forceinline__ unsigned long long pack2(float a) {
    unsigned long long r;
    asm("mov.b64 %0, {%1, %1};" : "=l"(r) : "r"(__float_as_uint(a)));
    return r;
}
__device__ __forceinline__ void ffma2(unsigned long long& d,
                                      unsigned long long a,
                                      unsigned long long b) {
    asm("fma.rn.f32x2 %0, %1, %2, %0;" : "+l"(d) : "l"(a), "l"(b));
}
__device__ __forceinline__ float2 unpack2(unsigned long long v) {
    unsigned lo, hi;
    asm("mov.b64 {%0, %1}, %2;" : "=r"(lo), "=r"(hi) : "l"(v));
    return make_float2(__uint_as_float(lo), __uint_as_float(hi));
}

// ---------------------------------------------------------------------------
// K_PREP: fused setup + h5 + init (independent work, blockIdx-partitioned)
// ---------------------------------------------------------------------------
__global__ void __launch_bounds__(256)
k_prep(const float* __restrict__ Wh,
       const float* __restrict__ Wnode,
       const float* __restrict__ attn_w,
       const float* __restrict__ rela,
       const float* __restrict__ Wr,
       const float* __restrict__ Wqr_w,
       const float* __restrict__ Wqr_b,
       const int*   __restrict__ q_rel,
       const float* __restrict__ hidden,
       const float* __restrict__ Ws,
       int nrel, int batch, int n_node)
{
    const int b = blockIdx.x;

    if (b < PREP_SETUP_BLKS) {
        int gtid   = b * blockDim.x + threadIdx.x;
        int stride = PREP_SETUP_BLKS * blockDim.x;

        for (int i = gtid; i < 64 * 66; i += stride) {
            int k = i / 66, c = i % 66;
            float s = 0.f;
            if (c < 64) {
                #pragma unroll 8
                for (int j = 0; j < 64; j++) s += Wh[k * 64 + j] * Wnode[j * 64 + c];
            } else {
                const float* w = attn_w + (c - 64) * 64;
                #pragma unroll 8
                for (int j = 0; j < 64; j++) s += Wh[k * 64 + j] * w[j];
            }
            g_Mext[i] = s;
        }
        for (int i = gtid; i < nrel * 5; i += stride) {
            int r = i / 5, j = i % 5;
            float s = 0.f;
            #pragma unroll 8
            for (int k = 0; k < 64; k++) s += rela[r * 64 + k] * Wr[k * 5 + j];
            g_crel[r * 8 + j] = s;
        }
        for (int i = gtid; i < batch * 5; i += stride) {
            int bb = i / 5, j = i % 5;
            int qr = q_rel[bb];
            float s = Wqr_b[j];
            #pragma unroll 8
            for (int k = 0; k < 64; k++) s += rela[qr * 64 + k] * Wqr_w[k * 5 + j];
            g_cq[bb * 8 + j] = s;
        }
        for (int i = gtid; i < NB_MAX; i += stride) g_sstate[i] = 0ull;
        if (gtid == 0) { g_max_enc = 0u; g_sum = 0.f; }
    } else if (b < PREP_SETUP_BLKS + PREP_H5_BLKS) {
        // --- H5 = hidden @ Ws (warp per node) ---
        const int lane = threadIdx.x & 31;
        float wsa[5], wsb[5];
        #pragma unroll
        for (int j = 0; j < 5; j++) {
            wsa[j] = __ldg(Ws + (2 * lane) * 5 + j);
            wsb[j] = __ldg(Ws + (2 * lane + 1) * 5 + j);
        }
        const int warps_total = PREP_H5_BLKS * (blockDim.x >> 5);
        int w = (b - PREP_SETUP_BLKS) * (blockDim.x >> 5) + (threadIdx.x >> 5);

        for (int node = w; node < n_node; node += warps_total) {
            const float2 h = *reinterpret_cast<const float2*>(
                hidden + (size_t)node * 64 + 2 * lane);
            float p0 = h.x * wsa[0] + h.y * wsb[0];
            float p1 = h.x * wsa[1] + h.y * wsb[1];
            float p2 = h.x * wsa[2] + h.y * wsb[2];
            float p3 = h.x * wsa[3] + h.y * wsb[3];
            float p4 = h.x * wsa[4] + h.y * wsb[4];
            #pragma unroll
            for (int off = 16; off > 0; off >>= 1) {
                p0 += __shfl_xor_sync(0xFFFFFFFFu, p0, off);
                p1 += __shfl_xor_sync(0xFFFFFFFFu, p1, off);
                p2 += __shfl_xor_sync(0xFFFFFFFFu, p2, off);
                p3 += __shfl_xor_sync(0xFFFFFFFFu, p3, off);
                p4 += __shfl_xor_sync(0xFFFFFFFFu, p4, off);
            }
            if (lane == 0) {
                float* dst = g_h5 + (size_t)node * 8;
                *reinterpret_cast<float4*>(dst) = make_float4(p0, p1, p2, p3);
                dst[4] = p4;
            }
        }
    } else {
        // --- init zeros: t, wsum, hist ---
        size_t gtid   = (size_t)(b - PREP_SETUP_BLKS - PREP_H5_BLKS) * blockDim.x
                        + threadIdx.x;
        size_t stride = (size_t)PREP_INIT_BLKS * blockDim.x;

        float4* tp = reinterpret_cast<float4*>(g_t);
        size_t  nt = (size_t)n_node * 16;
        float4  zv = make_float4(0.f, 0.f, 0.f, 0.f);
        for (size_t t = gtid; t < nt; t += stride) tp[t] = zv;
        for (size_t t = gtid; t < (size_t)n_node; t += stride) {
            g_hist[t] = 0;
            g_wsum[t] = 0.f;
        }
    }
}

// ---------------------------------------------------------------------------
// K2a: histogram over obj + stage compact edge tuples
// ---------------------------------------------------------------------------
__global__ void __launch_bounds__(256)
k_hist(const int* __restrict__ edges, int n_edge)
{
    int e = blockIdx.x * 256 + threadIdx.x;
    if (e >= n_edge) return;
    const int* ep = edges + (size_t)e * 6;
    int2 i01 = *reinterpret_cast<const int2*>(ep);
    int2 i23 = *reinterpret_cast<const int2*>(ep + 2);
    int2 i45 = *reinterpret_cast<const int2*>(ep + 4);
    g_estage[e] = make_int4(i01.x, i23.x, i45.x, i45.y);
    atomicAdd(&g_hist[i45.y], 1);
}

// ---------------------------------------------------------------------------
// K2b: SINGLE-PASS exclusive scan (decoupled lookback). nb <= 128 blocks,
//      all co-resident -> spin-wait is deadlock-free. All inter-block data
//      rides in one 64-bit atomic word: (status<<32)|value, status 1=agg 2=pfx.
// ---------------------------------------------------------------------------
__global__ void __launch_bounds__(SCAN_TPB)
k_scan(int n, int n_edge, int nb)
{
    __shared__ int wsum[8];
    __shared__ int s_excl;
    const int b    = blockIdx.x;
    const int tid  = threadIdx.x;
    const int base = b * SCAN_CHUNK + tid * SCAN_EPT;

    int v[SCAN_EPT];
    int s = 0;
    #pragma unroll
    for (int i = 0; i < SCAN_EPT; i++) {
        int idx = base + i;
        v[i] = (idx < n) ? g_hist[idx] : 0;
        s += v[i];
    }
    const int lane = tid & 31, wid = tid >> 5;
    int inc = s;
    #pragma unroll
    for (int off_ = 1; off_ < 32; off_ <<= 1) {
        int t = __shfl_up_sync(0xFFFFFFFFu, inc, off_);
        if (lane >= off_) inc += t;
    }
    if (lane == 31) wsum[wid] = inc;
    __syncthreads();
    if (wid == 0) {
        int ws = (lane < 8) ? wsum[lane] : 0;
        #pragma unroll
        for (int off_ = 1; off_ < 8; off_ <<= 1) {
            int t = __shfl_up_sync(0xFFFFFFFFu, ws, off_);
            if (lane >= off_) ws += t;
        }
        if (lane < 8) wsum[lane] = ws;     // inclusive warp totals
    }
    __syncthreads();
    const int run_local = inc - s + (wid > 0 ? wsum[wid - 1] : 0);
    const int agg = wsum[7];               // block aggregate

    // decoupled lookback (thread 0)
    if (tid == 0) {
        if (b == 0) {
            s_excl = 0;
            atomicExch(&g_sstate[0], (2ull << 32) | (unsigned)agg);
        } else {
            atomicExch(&g_sstate[b], (1ull << 32) | (unsigned)agg);
            int excl = 0;
            int p = b - 1;
            while (true) {
                unsigned long long w = atomicAdd(&g_sstate[p], 0ull);
                unsigned st = (unsigned)(w >> 32);
                if (st == 2u) { excl += (int)(unsigned)w; break; }
                if (st == 1u) { excl += (int)(unsigned)w; p--; }
                // st == 0: spin
            }
            s_excl = excl;
            atomicExch(&g_sstate[b], (2ull << 32) | (unsigned)(excl + agg));
        }
    }
    __syncthreads();

    int run = run_local + s_excl;
    #pragma unroll
    for (int i = 0; i < SCAN_EPT; i++) {
        int idx = base + i;
        if (idx < n) { g_off[idx] = run; g_cursor[idx] = run; }
        run += v[i];
    }
    if (b == nb - 1 && tid == SCAN_TPB - 1) g_off[n] = n_edge;
}

// ---------------------------------------------------------------------------
// K2e: scatter staged edges into obj-grouped packed records + inline alpha
// ---------------------------------------------------------------------------
__global__ void __launch_bounds__(256)
k_scatter(const float* __restrict__ wa, const float* __restrict__ wab,
          int n_edge)
{
    int e = blockIdx.x * 256 + threadIdx.x;
    if (e >= n_edge) return;
    const int4 st = g_estage[e];        // (r_idx, rel, sub, obj)
    const int r_idx = st.x, rel = st.y, sub = st.z, obj = st.w;

    int pos = atomicAdd(&g_cursor[obj], 1);

    const float4 h4 = *reinterpret_cast<const float4*>(g_h5 + (size_t)sub * 8);
    const float  h5 = g_h5[(size_t)sub * 8 + 4];
    const float4 c4 = *reinterpret_cast<const float4*>(g_crel + rel * 8);
    const float  c5 = g_crel[rel * 8 + 4];
    const float4 q4 = *reinterpret_cast<const float4*>(g_cq + r_idx * 8);
    const float  q5 = g_cq[r_idx * 8 + 4];

    float z = __ldg(wab);
    z += fmaxf(h4.x + c4.x + q4.x, 0.f) * __ldg(wa + 0);
    z += fmaxf(h4.y + c4.y + q4.y, 0.f) * __ldg(wa + 1);
    z += fmaxf(h4.z + c4.z + q4.z, 0.f) * __ldg(wa + 2);
    z += fmaxf(h4.w + c4.w + q4.w, 0.f) * __ldg(wa + 3);
    z += fmaxf(h5   + c5   + q5,   0.f) * __ldg(wa + 4);
    const float alpha = 1.f / (1.f + expf(-z));

    g_epack[pos] = make_int4(sub, rel, obj, __float_as_int(alpha));
}

// ---------------------------------------------------------------------------
// K3c: segment max — warp per node, serial edge walk; s0/s1 epilogue
// ---------------------------------------------------------------------------
__global__ void __launch_bounds__(256)
k_edge2(const float* __restrict__ hidden,
        const float* __restrict__ rela,
        int n_node)
{
    const int lane = threadIdx.x & 31;

    const float v0a = g_Mext[(2 * lane)     * 66 + 64];
    const float v1a = g_Mext[(2 * lane)     * 66 + 65];
    const float v0b = g_Mext[(2 * lane + 1) * 66 + 64];
    const float v1b = g_Mext[(2 * lane + 1) * 66 + 65];

    const int warps_total = gridDim.x * (blockDim.x >> 5);
    int w = blockIdx.x * (blockDim.x >> 5) + (threadIdx.x >> 5);

    for (int node = w; node < n_node; node += warps_total) {
        const int start = g_off[node];
        const int end   = g_off[node + 1];

        float m0 = -FLT_MAX, m1 = -FLT_MAX;
        for (int i = start; i < end; i++) {
            const int4 p = g_epack[i];                 // broadcast LDG.128
            const int   sub   = p.x;
            const int   rel   = p.y;
            const float alpha = __int_as_float(p.w);
            const float2 hs = *reinterpret_cast<const float2*>(hidden + (size_t)sub * 64 + 2 * lane);
            const float2 hr = *reinterpret_cast<const float2*>(rela   + (size_t)rel * 64 + 2 * lane);
            m0 = fmaxf(m0, alpha * (hs.x - hr.x));
            m1 = fmaxf(m1, alpha * (hs.y - hr.y));
        }
        float2 o = (end > start) ? make_float2(m0, m1) : make_float2(0.f, 0.f);
        *reinterpret_cast<float2*>(g_agg + (size_t)node * 64 + 2 * lane) = o;

        float s0p = o.x * v0a + o.y * v0b;
        float s1p = o.x * v1a + o.y * v1b;
        #pragma unroll
        for (int off = 16; off > 0; off >>= 1) {
            s0p += __shfl_xor_sync(0xFFFFFFFFu, s0p, off);
            s1p += __shfl_xor_sync(0xFFFFFFFFu, s1p, off);
        }
        if (lane == 0) {
            g_s0[node] = s0p;
            g_s1[node] = s1p;
        }
    }
}

// ---------------------------------------------------------------------------
// K5: scores + per-block online-softmax partials (ONE pass over edges)
// ---------------------------------------------------------------------------
__global__ void __launch_bounds__(256)
k_score2(const float* __restrict__ attn_b, int n_edge)
{
    __shared__ float red[8];
    __shared__ float s_bm;
    const int e    = blockIdx.x * 256 + threadIdx.x;
    const int lane = threadIdx.x & 31, wid = threadIdx.x >> 5;

    float sc = -FLT_MAX;
    if (e < n_edge) {
        const int4 p = g_epack[e];
        float s = g_s0[p.x] + g_s1[p.z] + __ldg(attn_b);
        sc = (s > 0.f) ? s : 0.2f * s;
        g_scores[e] = sc;
    }

    // block max
    float m = sc;
    #pragma unroll
    for (int off = 16; off > 0; off >>= 1)
        m = fmaxf(m, __shfl_xor_sync(0xFFFFFFFFu, m, off));
    if (lane == 0) red[wid] = m;
    __syncthreads();
    if (wid == 0) {
        float v = (lane < 8) ? red[lane] : -FLT_MAX;
        #pragma unroll
        for (int off = 4; off > 0; off >>= 1)
            v = fmaxf(v, __shfl_xor_sync(0xFFFFFFFFu, v, off));
        if (lane == 0) s_bm = v;
    }
    __syncthreads();
    const float bm = s_bm;

    // block sum of exp(sc - bm)
    float ex = (e < n_edge) ? expf(sc - bm) : 0.f;
    #pragma unroll
    for (int off = 16; off > 0; off >>= 1)
        ex += __shfl_xor_sync(0xFFFFFFFFu, ex, off);
    __syncthreads();
    if (lane == 0) red[wid] = ex;
    __syncthreads();
    if (wid == 0) {
        float v = (lane < 8) ? red[lane] : 0.f;
        #pragma unroll
        for (int off = 4; off > 0; off >>= 1)
            v += __shfl_xor_sync(0xFFFFFFFFu, v, off);
        if (lane == 0) {
            g_bmax[blockIdx.x] = bm;
            g_bsum[blockIdx.x] = v;
        }
    }
}

// ---------------------------------------------------------------------------
// K6: combine block partials -> global max & sum (single block)
// ---------------------------------------------------------------------------
__global__ void __launch_bounds__(256)
k_combine(int nblk)
{
    __shared__ float red[8];
    __shared__ float s_gm;
    const int tid = threadIdx.x;
    const int lane = tid & 31, wid = tid >> 5;

    float m = -FLT_MAX;
    for (int i = tid; i < nblk; i += 256) m = fmaxf(m, g_bmax[i]);
    #pragma unroll
    for (int off = 16; off > 0; off >>= 1)
        m = fmaxf(m, __shfl_xor_sync(0xFFFFFFFFu, m, off));
    if (lane == 0) red[wid] = m;
    __syncthreads();
    if (wid == 0) {
        float v = (lane < 8) ? red[lane] : -FLT_MAX;
        #pragma unroll
        for (int off = 4; off > 0; off >>= 1)
            v = fmaxf(v, __shfl_xor_sync(0xFFFFFFFFu, v, off));
        if (lane == 0) s_gm = v;
    }
    __syncthreads();
    const float gm = s_gm;

    float s = 0.f;
    for (int i = tid; i < nblk; i += 256)
        s += g_bsum[i] * expf(g_bmax[i] - gm);
    #pragma unroll
    for (int off = 16; off > 0; off >>= 1)
        s += __shfl_xor_sync(0xFFFFFFFFu, s, off);
    __syncthreads();
    if (lane == 0) red[wid] = s;
    __syncthreads();
    if (wid == 0) {
        float v = (lane < 8) ? red[lane] : 0.f;
        #pragma unroll
        for (int off = 4; off > 0; off >>= 1)
            v += __shfl_xor_sync(0xFFFFFFFFu, v, off);
        if (lane == 0) { g_max_enc = encf(gm); g_sum = v; }
    }
}

// ---------------------------------------------------------------------------
// K7: t-accumulation — t[sub] += w_e * agg[obj]; wsum[sub] += w_e
// ---------------------------------------------------------------------------
__global__ void __launch_bounds__(256)
k_taccum(int n_edge)
{
    const float inv = 1.f / g_sum;
    const float gm  = decf(g_max_enc);
    const int t = blockIdx.x * 256 + threadIdx.x;
    const int e = t >> 4;
    const int q = t & 15;
    if (e >= n_edge) return;

    const int4 p = g_epack[e];
    const int sub = p.x;
    const int obj = p.z;
    const float wgt = expf(__ldg(g_scores + e) - gm) * inv;
    const float4 m = *reinterpret_cast<const float4*>(
        g_agg + (size_t)obj * 64 + q * 4);
    float* op = g_t + (size_t)sub * 64 + q * 4;
    asm volatile("red.global.add.v4.f32 [%0], {%1, %2, %3, %4};"
                 :: "l"(op), "f"(wgt * m.x), "f"(wgt * m.y),
                    "f"(wgt * m.z), "f"(wgt * m.w)
                 : "memory");
    if (q == 0)
        asm volatile("red.global.add.f32 [%0], %1;"
                     :: "l"(g_wsum + sub), "f"(wgt) : "memory");
}

// ---------------------------------------------------------------------------
// K8: final GEMM — out = t@M + wsum*b; plain coalesced stores, all rows.
// ---------------------------------------------------------------------------
#define AS_STRIDE 68
#define GEMM_ROWS 256
#define GEMM_SMEM ((GEMM_ROWS * AS_STRIDE + 64 * 64) * 4)

__global__ void __launch_bounds__(256, 2)
k_gemm(int n_node, const float* __restrict__ Wnode_b, float* __restrict__ out)
{
    extern __shared__ float smem[];
    float* As  = smem;                            // 256 * 68
    float* MsL = smem + GEMM_ROWS * AS_STRIDE;    // 64 * 64, [k][half][tx][4]

    const int tid = threadIdx.x;
    for (int i = tid; i < 64 * 64; i += 256) {
        int k = i >> 6, c = i & 63;
        MsL[k * 64 + ((c & 4) ? 32 : 0) + (c >> 3) * 4 + (c & 3)] =
            g_Mext[k * 66 + c];
    }

    const int rb = blockIdx.x * GEMM_ROWS;
    const float4* src = reinterpret_cast<const float4*>(g_t + (size_t)rb * 64);
    const bool full = (rb + GEMM_ROWS <= n_node);

    #pragma unroll
    for (int t = 0; t < 16; t++) {
        int vidx = tid + t * 256;
        int r  = vidx >> 4;
        int k4 = (vidx & 15) * 4;
        float4 u = make_float4(0.f, 0.f, 0.f, 0.f);
        if (full || rb + r < n_node) u = src[vidx];
        *reinterpret_cast<float4*>(As + r * AS_STRIDE + k4) = u;
    }
    __syncthreads();

    const int tx = tid & 7;
    const int ty = tid >> 3;

    unsigned long long acc[8][4];
    #pragma unroll
    for (int i = 0; i < 8; i++)
        #pragma unroll
        for (int c = 0; c < 4; c++) acc[i][c] = 0ull;

    const float* arow  = As + ty * 8 * AS_STRIDE;
    const float* mbase = MsL + tx * 4;

    for (int k4 = 0; k4 < 64; k4 += 4) {
        float4 a[8];
        #pragma unroll
        for (int i = 0; i < 8; i++)
            a[i] = *reinterpret_cast<const float4*>(arow + i * AS_STRIDE + k4);

        #pragma unroll
        for (int kk = 0; kk < 4; kk++) {
            const ulonglong2 mp0 = *reinterpret_cast<const ulonglong2*>(mbase + (k4 + kk) * 64);
            const ulonglong2 mp1 = *reinterpret_cast<const ulonglong2*>(mbase + (k4 + kk) * 64 + 32);
            #pragma unroll
            for (int i = 0; i < 8; i++) {
                const float av = (kk == 0) ? a[i].x : (kk == 1) ? a[i].y
                               : (kk == 2) ? a[i].z : a[i].w;
                const unsigned long long aa = pack2(av);
                ffma2(acc[i][0], aa, mp0.x);
                ffma2(acc[i][1], aa, mp0.y);
                ffma2(acc[i][2], aa, mp1.x);
                ffma2(acc[i][3], aa, mp1.y);
            }
        }
    }

    const float4 b0 = *reinterpret_cast<const float4*>(Wnode_b + tx * 8);
    const float4 b1 = *reinterpret_cast<const float4*>(Wnode_b + tx * 8 + 4);
    #pragma unroll
    for (int i = 0; i < 8; i++) {
        int grow = rb + ty * 8 + i;
        if (grow < n_node) {
            const float ws = g_wsum[grow];
            float2 a0 = unpack2(acc[i][0]);
            float2 a1 = unpack2(acc[i][1]);
            float2 a2 = unpack2(acc[i][2]);
            float2 a3 = unpack2(acc[i][3]);
            float* op = out + (size_t)grow * 64 + tx * 8;
            *reinterpret_cast<float4*>(op) =
                make_float4(a0.x + ws * b0.x, a0.y + ws * b0.y,
                            a1.x + ws * b0.z, a1.y + ws * b0.w);
            *reinterpret_cast<float4*>(op + 4) =
                make_float4(a2.x + ws * b1.x, a2.y + ws * b1.y,
                            a3.x + ws * b1.z, a3.y + ws * b1.w);
        }
    }
}

// ---------------------------------------------------------------------------
// kernel_launch
// ---------------------------------------------------------------------------
extern "C" void kernel_launch(void* const* d_in, const int* in_sizes, int n_in,
                              void* d_out, int out_size)
{
    const float* hidden    = (const float*)d_in[0];
    const float* rela      = (const float*)d_in[1];
    const float* Ws        = (const float*)d_in[2];
    const float* Wr        = (const float*)d_in[3];
    const float* Wqr_w     = (const float*)d_in[4];
    const float* Wqr_b     = (const float*)d_in[5];
    const float* walpha_w  = (const float*)d_in[6];
    const float* walpha_b  = (const float*)d_in[7];
    const float* Wh        = (const float*)d_in[8];
    const float* attn_fc_w = (const float*)d_in[9];
    const float* attn_fc_b = (const float*)d_in[10];
    const float* Wnode_w   = (const float*)d_in[11];
    const float* Wnode_b   = (const float*)d_in[12];
    const int*   q_rel     = (const int*)d_in[14];
    const int*   edges     = (const int*)d_in[15];
    float*       out       = (float*)d_out;

    const int n_edge = in_sizes[15] / 6;
    const int n_node = in_sizes[16] / 2;
    const int nrel   = in_sizes[1] / 64;
    const int batch  = in_sizes[14];
    const int nb     = (n_node + SCAN_CHUNK - 1) / SCAN_CHUNK;
    const int neb    = (n_edge + 255) / 256;

    static bool attr_set = false;
    if (!attr_set) {
        cudaFuncSetAttribute(k_gemm, cudaFuncAttributeMaxDynamicSharedMemorySize,
                             GEMM_SMEM);
        attr_set = true;
    }

    // fused setup + h5 + init
    k_prep<<<PREP_BLKS, 256>>>(Wh, Wnode_w, attn_fc_w, rela, Wr, Wqr_w, Wqr_b,
                               q_rel, hidden, Ws, nrel, batch, n_node);

    // counting sort by obj: hist -> single-pass scan -> scatter(+alpha)
    k_hist<<<neb, 256>>>(edges, n_edge);
    k_scan<<<nb, SCAN_TPB>>>(n_node, n_edge, nb);
    k_scatter<<<neb, 256>>>(walpha_w, walpha_b, n_edge);

    // segment max + s0/s1 epilogue (warp per node)
    k_edge2<<<2368, 256>>>(hidden, rela, n_node);

    // online softmax: one edge pass + tiny combine
    k_score2<<<neb, 256>>>(attn_fc_b, n_edge);
    k_combine<<<1, 256>>>(neb);

    // t/wsum accumulation (16 threads/edge, RED.128, exp inline)
    k_taccum<<<(n_edge * 16 + 255) / 256, 256>>>(n_edge);

    // final GEMM: out = t@M + wsum*b (plain stores)
    k_gemm<<<(n_node + GEMM_ROWS - 1) / GEMM_ROWS, 256, GEMM_SMEM>>>(
        n_node, Wnode_b, out);
}